// round 9
// baseline (speedup 1.0000x reference)
#include <cuda_runtime.h>
#include <cuda_bf16.h>

// Dynamic relative-position-bias table: [head][idx], idx = di*15+dj, 6*225
__device__ float g_rpb[6 * 225];

// ---------------- packed f32x2 helpers (FFMA2 path, sm_100+) ----------------
static __device__ __forceinline__ unsigned long long pk2(float a, float b) {
    unsigned long long r;
    asm("mov.b64 %0, {%1,%2};" : "=l"(r) : "f"(a), "f"(b));
    return r;
}
static __device__ __forceinline__ void upk2(unsigned long long p, float &a, float &b) {
    asm("mov.b64 {%0,%1}, %2;" : "=f"(a), "=f"(b) : "l"(p));
}
static __device__ __forceinline__ void fma2(unsigned long long &d,
                                            unsigned long long a,
                                            unsigned long long b) {
    asm("fma.rn.f32x2 %0, %1, %2, %0;" : "+l"(d) : "l"(a), "l"(b));
}
static __device__ __forceinline__ unsigned long long add2(unsigned long long a,
                                                          unsigned long long b) {
    unsigned long long r;
    asm("add.rn.f32x2 %0, %1, %2;" : "=l"(r) : "l"(a), "l"(b));
    return r;
}

// ---------------- RPE MLP kernel: 225 rows, fully thread-local ----------------
static __device__ __forceinline__ void ln_relu12(float *x, const float *g, const float *b) {
    float m = 0.f;
#pragma unroll
    for (int j = 0; j < 12; j++) m += x[j];
    m *= (1.0f / 12.0f);
    float v = 0.f;
#pragma unroll
    for (int j = 0; j < 12; j++) { float d = x[j] - m; v += d * d; }
    v *= (1.0f / 12.0f);
    float inv = rsqrtf(v + 1e-5f);
#pragma unroll
    for (int j = 0; j < 12; j++) {
        float t = (x[j] - m) * inv * g[j] + b[j];
        x[j] = fmaxf(t, 0.f);
    }
}

__global__ void rpe_mlp_kernel(const float *__restrict__ w_proj, const float *__restrict__ b_proj,
                               const float *__restrict__ ln1_g, const float *__restrict__ ln1_b,
                               const float *__restrict__ w1,    const float *__restrict__ b1,
                               const float *__restrict__ ln2_g, const float *__restrict__ ln2_b,
                               const float *__restrict__ w2,    const float *__restrict__ b2,
                               const float *__restrict__ ln3_g, const float *__restrict__ ln3_b,
                               const float *__restrict__ w3,    const float *__restrict__ b3) {
    int r = threadIdx.x;
    if (r >= 225) return;
    float in0 = (float)(r / 15 - 7);   // bh = i - (HS-1)
    float in1 = (float)(r % 15 - 7);   // bw
    float x[12], y[12];
#pragma unroll
    for (int j = 0; j < 12; j++)
        x[j] = in0 * w_proj[j] + in1 * w_proj[12 + j] + b_proj[j];
    ln_relu12(x, ln1_g, ln1_b);
#pragma unroll
    for (int j = 0; j < 12; j++) {
        float acc = b1[j];
#pragma unroll
        for (int i = 0; i < 12; i++) acc += x[i] * w1[i * 12 + j];
        y[j] = acc;
    }
    ln_relu12(y, ln2_g, ln2_b);
#pragma unroll
    for (int j = 0; j < 12; j++) {
        float acc = b2[j];
#pragma unroll
        for (int i = 0; i < 12; i++) acc += y[i] * w2[i * 12 + j];
        x[j] = acc;
    }
    ln_relu12(x, ln3_g, ln3_b);
#pragma unroll
    for (int h = 0; h < 6; h++) {
        float acc = b3[h];
#pragma unroll
        for (int i = 0; i < 12; i++) acc += x[i] * w3[i * 6 + h];
        g_rpb[h * 225 + r] = acc;
    }
}

// ---------------- windowed attention kernel ----------------
// grid.x = B * (H/8) * (W/8) * NH = 4*32*32*6 = 24576 ; block = 64 threads
// CTA = one (window, head). Thread = one query row (n = 0..63).
#define QK_SCALE 0.17677669529663687f  // 32^-0.5

__global__ __launch_bounds__(64) void attn_kernel(const float *__restrict__ Q,
                                                  const float *__restrict__ K,
                                                  const float *__restrict__ V,
                                                  float *__restrict__ O) {
    __shared__ __align__(16) float sk[64][32];
    __shared__ __align__(16) float sv[64][32];
    __shared__ float sq[64][33];   // padded: conflict-free row reads/writes
    __shared__ float srpb[232];

    int head = blockIdx.x % 6;
    int win  = blockIdx.x / 6;
    int b    = win >> 10;          // 1024 windows per image
    int whb  = (win >> 5) & 31;
    int wwb  = win & 31;
    int tid = threadIdx.x, lane = tid & 31, wp = tid >> 5;

    for (int i = tid; i < 225; i += 64) srpb[i] = g_rpb[head * 225 + i];

    long base = (((long)b) << 16) * 192 + head * 32;  // b*L*C + head*hd
    int r0 = whb << 3, c0 = wwb << 3;
    for (int p = wp; p < 64; p += 2) {
        int rr = r0 + (p >> 3), cc = c0 + (p & 7);
        long g = base + (long)(rr * 256 + cc) * 192 + lane;
        sq[p][lane] = Q[g] * QK_SCALE;
        sk[p][lane] = K[g];
        sv[p][lane] = V[g];
    }
    __syncthreads();

    const int n = tid;
    unsigned long long qp[16];
#pragma unroll
    for (int i = 0; i < 16; i++) qp[i] = pk2(sq[n][2 * i], sq[n][2 * i + 1]);
    const int i1 = n >> 3, j1 = n & 7;

    // ---- S = q·kT + rpb, row n in registers ----
    float s[64];
#pragma unroll
    for (int m = 0; m < 64; m++) {
        const ulonglong2 *kr = reinterpret_cast<const ulonglong2 *>(sk[m]);
        unsigned long long a0 = 0ull, a1 = 0ull;
#pragma unroll
        for (int j = 0; j < 8; j++) {
            ulonglong2 kk = kr[j];         // 4 k-floats, broadcast (conflict-free)
            fma2(a0, qp[2 * j],     kk.x);
            fma2(a1, qp[2 * j + 1], kk.y);
        }
        unsigned long long at = add2(a0, a1);
        float lo, hi; upk2(at, lo, hi);
        int di = i1 - (m >> 3) + 7;
        int dj = j1 - (m & 7) + 7;
        s[m] = lo + hi + srpb[di * 15 + dj];
    }

    // ---- softmax over m (exact fp32) ----
    float mx = s[0];
#pragma unroll
    for (int m = 1; m < 64; m++) mx = fmaxf(mx, s[m]);
    float sum = 0.f;
#pragma unroll
    for (int m = 0; m < 64; m++) { float e = __expf(s[m] - mx); s[m] = e; sum += e; }
    float inv = 1.0f / sum;

    // ---- O = P · V ----
    unsigned long long acc[16];
#pragma unroll
    for (int i = 0; i < 16; i++) acc[i] = 0ull;
#pragma unroll
    for (int m = 0; m < 64; m++) {
        unsigned long long pm = pk2(s[m], s[m]);
        const ulonglong2 *vr = reinterpret_cast<const ulonglong2 *>(sv[m]);
#pragma unroll
        for (int j = 0; j < 8; j++) {
            ulonglong2 vv = vr[j];
            fma2(acc[2 * j],     pm, vv.x);
            fma2(acc[2 * j + 1], pm, vv.y);
        }
    }

    // stage output through sq for coalesced global stores
    __syncthreads();
#pragma unroll
    for (int i = 0; i < 16; i++) {
        float a, bb; upk2(acc[i], a, bb);
        sq[n][2 * i]     = a * inv;
        sq[n][2 * i + 1] = bb * inv;
    }
    __syncthreads();
    for (int p = wp; p < 64; p += 2) {
        int rr = r0 + (p >> 3), cc = c0 + (p & 7);
        long g = base + (long)(rr * 256 + cc) * 192 + lane;
        O[g] = sq[p][lane];
    }
}

// ---------------- launch ----------------
extern "C" void kernel_launch(void *const *d_in, const int *in_sizes, int n_in,
                              void *d_out, int out_size) {
    const float *q = (const float *)d_in[0];
    const float *k = (const float *)d_in[1];
    const float *v = (const float *)d_in[2];
    // d_in[3]=H, d_in[4]=W (int32, fixed 256x256 for this problem)
    const float *w_proj = (const float *)d_in[5];
    const float *b_proj = (const float *)d_in[6];
    const float *ln1_g  = (const float *)d_in[7];
    const float *ln1_b  = (const float *)d_in[8];
    const float *w1     = (const float *)d_in[9];
    const float *b1     = (const float *)d_in[10];
    const float *ln2_g  = (const float *)d_in[11];
    const float *ln2_b  = (const float *)d_in[12];
    const float *w2     = (const float *)d_in[13];
    const float *b2     = (const float *)d_in[14];
    const float *ln3_g  = (const float *)d_in[15];
    const float *ln3_b  = (const float *)d_in[16];
    const float *w3     = (const float *)d_in[17];
    const float *b3     = (const float *)d_in[18];
    float *out = (float *)d_out;

    rpe_mlp_kernel<<<1, 256>>>(w_proj, b_proj, ln1_g, ln1_b, w1, b1,
                               ln2_g, ln2_b, w2, b2, ln3_g, ln3_b, w3, b3);

    // B=4, H=W=256 -> 4*32*32 windows * 6 heads
    attn_kernel<<<24576, 64>>>(q, k, v, out);
}

// round 10
// speedup vs baseline: 1.5547x; 1.5547x over previous
#include <cuda_runtime.h>

__device__ float g_rpb[6 * 225];
typedef unsigned long long ull;
#define QK_SCALE 0.17677669529663687f

static __device__ __forceinline__ ull pk2(float a, float b) {
    ull r; asm("mov.b64 %0, {%1,%2};" : "=l"(r) : "f"(a), "f"(b)); return r;
}
static __device__ __forceinline__ void upk2(ull p, float &a, float &b) {
    asm("mov.b64 {%0,%1}, %2;" : "=f"(a), "=f"(b) : "l"(p));
}
static __device__ __forceinline__ void fma2(ull &d, ull a, ull b) {
    asm("fma.rn.f32x2 %0, %1, %2, %0;" : "+l"(d) : "l"(a), "l"(b));
}

static __device__ __forceinline__ void ln_relu12(float *x, const float *g, const float *b) {
    float m = 0.f;
#pragma unroll
    for (int j = 0; j < 12; j++) m += x[j];
    m *= (1.0f / 12.0f);
    float v = 0.f;
#pragma unroll
    for (int j = 0; j < 12; j++) { float d = x[j] - m; v += d * d; }
    v *= (1.0f / 12.0f);
    float inv = rsqrtf(v + 1e-5f);
#pragma unroll
    for (int j = 0; j < 12; j++) x[j] = fmaxf((x[j] - m) * inv * g[j] + b[j], 0.f);
}

__global__ void rpe_mlp_kernel(const float *__restrict__ w_proj, const float *__restrict__ b_proj,
                               const float *__restrict__ ln1_g, const float *__restrict__ ln1_b,
                               const float *__restrict__ w1,    const float *__restrict__ b1,
                               const float *__restrict__ ln2_g, const float *__restrict__ ln2_b,
                               const float *__restrict__ w2,    const float *__restrict__ b2,
                               const float *__restrict__ ln3_g, const float *__restrict__ ln3_b,
                               const float *__restrict__ w3,    const float *__restrict__ b3) {
    int r = threadIdx.x;
    if (r >= 225) return;
    float in0 = (float)(r / 15 - 7), in1 = (float)(r % 15 - 7);
    float x[12], y[12];
#pragma unroll
    for (int j = 0; j < 12; j++) x[j] = in0 * w_proj[j] + in1 * w_proj[12 + j] + b_proj[j];
    ln_relu12(x, ln1_g, ln1_b);
#pragma unroll
    for (int j = 0; j < 12; j++) {
        float a = b1[j];
#pragma unroll
        for (int i = 0; i < 12; i++) a += x[i] * w1[i * 12 + j];
        y[j] = a;
    }
    ln_relu12(y, ln2_g, ln2_b);
#pragma unroll
    for (int j = 0; j < 12; j++) {
        float a = b2[j];
#pragma unroll
        for (int i = 0; i < 12; i++) a += y[i] * w2[i * 12 + j];
        x[j] = a;
    }
    ln_relu12(x, ln3_g, ln3_b);
#pragma unroll
    for (int h = 0; h < 6; h++) {
        float a = b3[h];
#pragma unroll
        for (int i = 0; i < 12; i++) a += x[i] * w3[i * 6 + h];
        g_rpb[h * 225 + r] = a;
    }
}

// CTA = (window, head); 64 threads; thread (ti,tj) owns S[8ti+r][8tj+c].
__global__ __launch_bounds__(64, 8) void attn_kernel(const float *__restrict__ Q,
                                                     const float *__restrict__ K,
                                                     const float *__restrict__ V,
                                                     float *__restrict__ O) {
    __shared__ __align__(16) float sQK[4352];   // qT[32][68] ++ kT[32][68]; reused as pT[64][68]
    __shared__ __align__(16) float sv[64][32];
    __shared__ float srpb[228];
    float *qT = sQK, *kT = sQK + 32 * 68, *pT = sQK;

    int head = blockIdx.x % 6, win = blockIdx.x / 6;
    int b = win >> 10, whb = (win >> 5) & 31, wwb = win & 31;
    int tid = threadIdx.x, lane = tid & 31, wp = tid >> 5;
    int ti = tid >> 3, tj = tid & 7;

    for (int i = tid; i < 225; i += 64) srpb[i] = g_rpb[head * 225 + i];

    long base = ((long)b << 16) * 192 + head * 32;
    int r0 = whb << 3, c0 = wwb << 3;
    for (int p = wp; p < 64; p += 2) {
        long g = base + (long)((r0 + (p >> 3)) * 256 + c0 + (p & 7)) * 192 + lane;
        qT[lane * 68 + p] = Q[g] * QK_SCALE;
        kT[lane * 68 + p] = K[g];
        sv[p][lane] = V[g];
    }
    __syncthreads();

    // ---- S = qk^T : 8x8 tile, packed over m-pairs ----
    ull sacc[8][4];
#pragma unroll
    for (int r = 0; r < 8; r++)
#pragma unroll
        for (int cp = 0; cp < 4; cp++) sacc[r][cp] = 0ull;
#pragma unroll
    for (int ch = 0; ch < 32; ch++) {
        const float4 *qr = reinterpret_cast<const float4 *>(qT + ch * 68 + 8 * ti);
        float4 q0 = qr[0], q1 = qr[1];
        const ulonglong2 *kr = reinterpret_cast<const ulonglong2 *>(kT + ch * 68 + 8 * tj);
        ulonglong2 k0 = kr[0], k1 = kr[1];
        float qv[8] = {q0.x, q0.y, q0.z, q0.w, q1.x, q1.y, q1.z, q1.w};
#pragma unroll
        for (int r = 0; r < 8; r++) {
            ull pm = pk2(qv[r], qv[r]);
            fma2(sacc[r][0], pm, k0.x); fma2(sacc[r][1], pm, k0.y);
            fma2(sacc[r][2], pm, k1.x); fma2(sacc[r][3], pm, k1.y);
        }
    }

    // ---- +rpb (register-resident), softmax via shfl over tj-group ----
    float s[8][8], inv_[8];
    float rb[15];
    int di = ti - tj + 7;
#pragma unroll
    for (int i = 0; i < 15; i++) rb[i] = srpb[di * 15 + i];
#pragma unroll
    for (int r = 0; r < 8; r++) {
#pragma unroll
        for (int cp = 0; cp < 4; cp++) upk2(sacc[r][cp], s[r][2 * cp], s[r][2 * cp + 1]);
#pragma unroll
        for (int c = 0; c < 8; c++) s[r][c] += rb[r - c + 7];
        float mx = s[r][0];
#pragma unroll
        for (int c = 1; c < 8; c++) mx = fmaxf(mx, s[r][c]);
        mx = fmaxf(mx, __shfl_xor_sync(0xffffffffu, mx, 1));
        mx = fmaxf(mx, __shfl_xor_sync(0xffffffffu, mx, 2));
        mx = fmaxf(mx, __shfl_xor_sync(0xffffffffu, mx, 4));
        float sum = 0.f;
#pragma unroll
        for (int c = 0; c < 8; c++) { s[r][c] = __expf(s[r][c] - mx); sum += s[r][c]; }
        sum += __shfl_xor_sync(0xffffffffu, sum, 1);
        sum += __shfl_xor_sync(0xffffffffu, sum, 2);
        sum += __shfl_xor_sync(0xffffffffu, sum, 4);
        inv_[r] = 1.0f / sum;
    }

    // ---- store P transposed (pT[m][n], XOR-swizzled blocks) ----
    __syncthreads();   // qT/kT reads complete before overwrite
    float4 *p4 = reinterpret_cast<float4 *>(pT);
#pragma unroll
    for (int c = 0; c < 8; c++) {
        int m = 8 * tj + c;
        int blk = 17 * m + 2 * ti;
        p4[blk ^ tj]       = make_float4(s[0][c], s[1][c], s[2][c], s[3][c]);
        p4[(blk + 1) ^ tj] = make_float4(s[4][c], s[5][c], s[6][c], s[7][c]);
    }
    __syncthreads();

    // ---- O = P V : thread computes O[8ti+r][4tj..4tj+3] ----
    ull acc[8][2];
#pragma unroll
    for (int r = 0; r < 8; r++) { acc[r][0] = 0ull; acc[r][1] = 0ull; }
    const float4 *pr4 = reinterpret_cast<const float4 *>(pT);
#pragma unroll 16
    for (int m = 0; m < 64; m++) {
        int key = m >> 3, blk = 17 * m + 2 * ti;
        float4 p0 = pr4[blk ^ key], p1 = pr4[(blk + 1) ^ key];
        ulonglong2 vv = *reinterpret_cast<const ulonglong2 *>(&sv[m][4 * tj]);
        float pv[8] = {p0.x, p0.y, p0.z, p0.w, p1.x, p1.y, p1.z, p1.w};
#pragma unroll
        for (int r = 0; r < 8; r++) {
            ull pm = pk2(pv[r], pv[r]);
            fma2(acc[r][0], pm, vv.x);
            fma2(acc[r][1], pm, vv.y);
        }
    }

    // ---- coalesced STG.128 straight from regs ----
#pragma unroll
    for (int r = 0; r < 8; r++) {
        float o0, o1, o2, o3;
        upk2(acc[r][0], o0, o1);
        upk2(acc[r][1], o2, o3);
        float iv = inv_[r];
        long g = base + (long)((r0 + ti) * 256 + c0 + r) * 192 + 4 * tj;
        *reinterpret_cast<float4 *>(const_cast<float *>(O + g)) =
            make_float4(o0 * iv, o1 * iv, o2 * iv, o3 * iv);
    }
}

extern "C" void kernel_launch(void *const *d_in, const int *in_sizes, int n_in,
                              void *d_out, int out_size) {
    const float *q = (const float *)d_in[0];
    const float *k = (const float *)d_in[1];
    const float *v = (const float *)d_in[2];
    rpe_mlp_kernel<<<1, 256>>>((const float *)d_in[5], (const float *)d_in[6],
                               (const float *)d_in[7], (const float *)d_in[8],
                               (const float *)d_in[9], (const float *)d_in[10],
                               (const float *)d_in[11], (const float *)d_in[12],
                               (const float *)d_in[13], (const float *)d_in[14],
                               (const float *)d_in[15], (const float *)d_in[16],
                               (const float *)d_in[17], (const float *)d_in[18]);
    attn_kernel<<<24576, 64>>>(q, k, v, (float *)d_out);
}

// round 12
// speedup vs baseline: 1.7262x; 1.1103x over previous
#include <cuda_runtime.h>

__device__ float g_rpb[6 * 225];
typedef unsigned long long ull;
#define QK_SCALE 0.17677669529663687f

static __device__ __forceinline__ ull pk2(float a, float b) {
    ull r; asm("mov.b64 %0, {%1,%2};" : "=l"(r) : "f"(a), "f"(b)); return r;
}
static __device__ __forceinline__ void upk2(ull p, float &a, float &b) {
    asm("mov.b64 {%0,%1}, %2;" : "=f"(a), "=f"(b) : "l"(p));
}
static __device__ __forceinline__ void fma2(ull &d, ull a, ull b) {
    asm("fma.rn.f32x2 %0, %1, %2, %0;" : "+l"(d) : "l"(a), "l"(b));
}

static __device__ __forceinline__ void ln_relu12(float *x, const float *g, const float *b) {
    float m = 0.f;
#pragma unroll
    for (int j = 0; j < 12; j++) m += x[j];
    m *= (1.0f / 12.0f);
    float v = 0.f;
#pragma unroll
    for (int j = 0; j < 12; j++) { float d = x[j] - m; v += d * d; }
    v *= (1.0f / 12.0f);
    float inv = rsqrtf(v + 1e-5f);
#pragma unroll
    for (int j = 0; j < 12; j++) x[j] = fmaxf((x[j] - m) * inv * g[j] + b[j], 0.f);
}

__global__ void rpe_mlp_kernel(const float *__restrict__ w_proj, const float *__restrict__ b_proj,
                               const float *__restrict__ ln1_g, const float *__restrict__ ln1_b,
                               const float *__restrict__ w1,    const float *__restrict__ b1,
                               const float *__restrict__ ln2_g, const float *__restrict__ ln2_b,
                               const float *__restrict__ w2,    const float *__restrict__ b2,
                               const float *__restrict__ ln3_g, const float *__restrict__ ln3_b,
                               const float *__restrict__ w3,    const float *__restrict__ b3) {
    int r = threadIdx.x;
    if (r >= 225) return;
    float in0 = (float)(r / 15 - 7), in1 = (float)(r % 15 - 7);
    float x[12], y[12];
#pragma unroll
    for (int j = 0; j < 12; j++) x[j] = in0 * w_proj[j] + in1 * w_proj[12 + j] + b_proj[j];
    ln_relu12(x, ln1_g, ln1_b);
#pragma unroll
    for (int j = 0; j < 12; j++) {
        float a = b1[j];
#pragma unroll
        for (int i = 0; i < 12; i++) a += x[i] * w1[i * 12 + j];
        y[j] = a;
    }
    ln_relu12(y, ln2_g, ln2_b);
#pragma unroll
    for (int j = 0; j < 12; j++) {
        float a = b2[j];
#pragma unroll
        for (int i = 0; i < 12; i++) a += y[i] * w2[i * 12 + j];
        x[j] = a;
    }
    ln_relu12(x, ln3_g, ln3_b);
#pragma unroll
    for (int h = 0; h < 6; h++) {
        float a = b3[h];
#pragma unroll
        for (int i = 0; i < 12; i++) a += x[i] * w3[i * 6 + h];
        g_rpb[h * 225 + r] = a;
    }
}

// CTA = (window, head); 64 threads; thread (ti,tj) owns S[8ti+r][8tj+c].
// qT/kT column layout is bit-permuted: logical pixel p sits at column
// phys(p) = (p&4)*8 + (p>>3)*4 + (p&3)  -> conflict-free k-frag reads.
__global__ __launch_bounds__(64, 8) void attn_kernel(const float *__restrict__ Q,
                                                     const float *__restrict__ K,
                                                     const float *__restrict__ V,
                                                     float *__restrict__ O) {
    __shared__ __align__(16) float sQK[4352];   // qT[32][68] ++ kT[32][68]; reused as pT[64 rows of 17 blk]
    __shared__ __align__(16) float sv[64][32];
    __shared__ float srpb[228];
    float *qT = sQK, *kT = sQK + 32 * 68, *pT = sQK;

    int head = blockIdx.x % 6, win = blockIdx.x / 6;
    int b = win >> 10, whb = (win >> 5) & 31, wwb = win & 31;
    int tid = threadIdx.x, lane = tid & 31, wp = tid >> 5;
    int ti = tid >> 3, tj = tid & 7;

    for (int i = tid; i < 225; i += 64) srpb[i] = g_rpb[head * 225 + i];

    long base = ((long)b << 16) * 192 + head * 32;
    int r0 = whb << 3, c0 = wwb << 3;

    // ---- load + register-staged transpose (STS.128, conflict-minimal) ----
#pragma unroll
    for (int g4 = 0; g4 < 8; g4++) {
        float qv4[4], kv4[4];
#pragma unroll
        for (int j = 0; j < 4; j++) {
            int p = wp * 32 + g4 * 4 + j;
            long g = base + (long)((r0 + (p >> 3)) * 256 + c0 + (p & 7)) * 192 + lane;
            qv4[j] = Q[g] * QK_SCALE;
            kv4[j] = K[g];
            sv[p][lane] = V[g];
        }
        // phys column of this 4-group: ((wp*8+g4)&1)*32 + ((wp*8+g4)>>1)*4
        int col = (g4 & 1) * 32 + (wp * 4 + (g4 >> 1)) * 4;
        *reinterpret_cast<float4 *>(qT + lane * 68 + col) = make_float4(qv4[0], qv4[1], qv4[2], qv4[3]);
        *reinterpret_cast<float4 *>(kT + lane * 68 + col) = make_float4(kv4[0], kv4[1], kv4[2], kv4[3]);
    }
    __syncthreads();

    // ---- S = qk^T : 8x8 tile, packed over m-pairs ----
    ull sacc[8][4];
#pragma unroll
    for (int r = 0; r < 8; r++)
#pragma unroll
        for (int cp = 0; cp < 4; cp++) sacc[r][cp] = 0ull;
#pragma unroll
    for (int ch = 0; ch < 32; ch++) {
        const float *qrow = qT + ch * 68;
        float4 q0 = *reinterpret_cast<const float4 *>(qrow + 4 * ti);        // rows 8ti+0..3
        float4 q1 = *reinterpret_cast<const float4 *>(qrow + 32 + 4 * ti);   // rows 8ti+4..7
        const float *krow = kT + ch * 68;
        ulonglong2 k0 = *reinterpret_cast<const ulonglong2 *>(krow + 4 * tj);       // m 8tj+0..3
        ulonglong2 k1 = *reinterpret_cast<const ulonglong2 *>(krow + 32 + 4 * tj);  // m 8tj+4..7
        float qv[8] = {q0.x, q0.y, q0.z, q0.w, q1.x, q1.y, q1.z, q1.w};
#pragma unroll
        for (int r = 0; r < 8; r++) {
            ull pm = pk2(qv[r], qv[r]);
            fma2(sacc[r][0], pm, k0.x); fma2(sacc[r][1], pm, k0.y);
            fma2(sacc[r][2], pm, k1.x); fma2(sacc[r][3], pm, k1.y);
        }
    }

    // ---- +rpb (register-resident), softmax via shfl over tj-octet ----
    float s[8][8], inv_[8];
    float rb[15];
    int di = ti - tj + 7;
#pragma unroll
    for (int i = 0; i < 15; i++) rb[i] = srpb[di * 15 + i];
#pragma unroll
    for (int r = 0; r < 8; r++) {
#pragma unroll
        for (int cp = 0; cp < 4; cp++) upk2(sacc[r][cp], s[r][2 * cp], s[r][2 * cp + 1]);
#pragma unroll
        for (int c = 0; c < 8; c++) s[r][c] += rb[r - c + 7];
        float mx = s[r][0];
#pragma unroll
        for (int c = 1; c < 8; c++) mx = fmaxf(mx, s[r][c]);
        mx = fmaxf(mx, __shfl_xor_sync(0xffffffffu, mx, 1));
        mx = fmaxf(mx, __shfl_xor_sync(0xffffffffu, mx, 2));
        mx = fmaxf(mx, __shfl_xor_sync(0xffffffffu, mx, 4));
        float sum = 0.f;
#pragma unroll
        for (int c = 0; c < 8; c++) { s[r][c] = __expf(s[r][c] - mx); sum += s[r][c]; }
        sum += __shfl_xor_sync(0xffffffffu, sum, 1);
        sum += __shfl_xor_sync(0xffffffffu, sum, 2);
        sum += __shfl_xor_sync(0xffffffffu, sum, 4);
        inv_[r] = 1.0f / sum;
    }

    // ---- store P transposed (pT[m] row of 17 float4-blocks, XOR-swizzled) ----
    __syncthreads();   // qT/kT reads complete before overwrite
    float4 *p4 = reinterpret_cast<float4 *>(pT);
#pragma unroll
    for (int c = 0; c < 8; c++) {
        int m = 8 * tj + c;
        int blk = 17 * m + 2 * ti;
        p4[blk ^ tj]       = make_float4(s[0][c], s[1][c], s[2][c], s[3][c]);
        p4[(blk + 1) ^ tj] = make_float4(s[4][c], s[5][c], s[6][c], s[7][c]);
    }
    __syncthreads();

    // ---- O = P V : thread computes O[8ti+r][4tj..4tj+3] ----
    ull acc[8][2];
#pragma unroll
    for (int r = 0; r < 8; r++) { acc[r][0] = 0ull; acc[r][1] = 0ull; }
    const float4 *pr4 = reinterpret_cast<const float4 *>(pT);
#pragma unroll 16
    for (int m = 0; m < 64; m++) {
        int key = m >> 3, blk = 17 * m + 2 * ti;
        float4 p0 = pr4[blk ^ key], p1 = pr4[(blk + 1) ^ key];
        ulonglong2 vv = *reinterpret_cast<const ulonglong2 *>(&sv[m][4 * tj]);
        float pv[8] = {p0.x, p0.y, p0.z, p0.w, p1.x, p1.y, p1.z, p1.w};
#pragma unroll
        for (int r = 0; r < 8; r++) {
            ull pm = pk2(pv[r], pv[r]);
            fma2(acc[r][0], pm, vv.x);
            fma2(acc[r][1], pm, vv.y);
        }
    }

    // ---- coalesced STG.128 straight from regs ----
#pragma unroll
    for (int r = 0; r < 8; r++) {
        float o0, o1, o2, o3;
        upk2(acc[r][0], o0, o1);
        upk2(acc[r][1], o2, o3);
        float iv = inv_[r];
        long g = base + (long)((r0 + ti) * 256 + c0 + r) * 192 + 4 * tj;
        *reinterpret_cast<float4 *>(const_cast<float *>(O + g)) =
            make_float4(o0 * iv, o1 * iv, o2 * iv, o3 * iv);
    }
}

extern "C" void kernel_launch(void *const *d_in, const int *in_sizes, int n_in,
                              void *d_out, int out_size) {
    const float *q = (const float *)d_in[0];
    const float *k = (const float *)d_in[1];
    const float *v = (const float *)d_in[2];
    rpe_mlp_kernel<<<1, 256>>>((const float *)d_in[5], (const float *)d_in[6],
                               (const float *)d_in[7], (const float *)d_in[8],
                               (const float *)d_in[9], (const float *)d_in[10],
                               (const float *)d_in[11], (const float *)d_in[12],
                               (const float *)d_in[13], (const float *)d_in[14],
                               (const float *)d_in[15], (const float *)d_in[16],
                               (const float *)d_in[17], (const float *)d_in[18]);
    attn_kernel<<<24576, 64>>>(q, k, v, (float *)d_out);
}

// round 13
// speedup vs baseline: 3.7895x; 2.1953x over previous
#include <cuda_runtime.h>
#include <cuda_fp16.h>

__device__ float g_rpb[6 * 225];
#define QK_SCALE 0.17677669529663687f

static __device__ __forceinline__ unsigned smem_u32(const void *p) {
    unsigned a;
    asm("{ .reg .u64 t; cvta.to.shared.u64 t, %1; cvt.u32.u64 %0, t; }" : "=r"(a) : "l"(p));
    return a;
}
static __device__ __forceinline__ unsigned pkh2(float lo, float hi) {
    unsigned r;
    asm("cvt.rn.f16x2.f32 %0, %1, %2;" : "=r"(r) : "f"(hi), "f"(lo));
    return r;
}
static __device__ __forceinline__ uint4 ldm4(unsigned addr) {
    uint4 r;
    asm volatile("ldmatrix.sync.aligned.m8n8.x4.shared.b16 {%0,%1,%2,%3}, [%4];"
                 : "=r"(r.x), "=r"(r.y), "=r"(r.z), "=r"(r.w) : "r"(addr));
    return r;
}
static __device__ __forceinline__ uint4 ldm4t(unsigned addr) {
    uint4 r;
    asm volatile("ldmatrix.sync.aligned.m8n8.x4.trans.shared.b16 {%0,%1,%2,%3}, [%4];"
                 : "=r"(r.x), "=r"(r.y), "=r"(r.z), "=r"(r.w) : "r"(addr));
    return r;
}
static __device__ __forceinline__ void mmaf16(float *c, uint4 a, unsigned b0, unsigned b1) {
    asm volatile("mma.sync.aligned.m16n8k16.row.col.f32.f16.f16.f32 "
                 "{%0,%1,%2,%3}, {%4,%5,%6,%7}, {%8,%9}, {%0,%1,%2,%3};"
                 : "+f"(c[0]), "+f"(c[1]), "+f"(c[2]), "+f"(c[3])
                 : "r"(a.x), "r"(a.y), "r"(a.z), "r"(a.w), "r"(b0), "r"(b1));
}

static __device__ __forceinline__ void ln_relu12(float *x, const float *g, const float *b) {
    float m = 0.f;
#pragma unroll
    for (int j = 0; j < 12; j++) m += x[j];
    m *= (1.0f / 12.0f);
    float v = 0.f;
#pragma unroll
    for (int j = 0; j < 12; j++) { float d = x[j] - m; v += d * d; }
    v *= (1.0f / 12.0f);
    float inv = rsqrtf(v + 1e-5f);
#pragma unroll
    for (int j = 0; j < 12; j++) x[j] = fmaxf((x[j] - m) * inv * g[j] + b[j], 0.f);
}

__global__ void rpe_mlp_kernel(const float *__restrict__ w_proj, const float *__restrict__ b_proj,
                               const float *__restrict__ ln1_g, const float *__restrict__ ln1_b,
                               const float *__restrict__ w1,    const float *__restrict__ b1,
                               const float *__restrict__ ln2_g, const float *__restrict__ ln2_b,
                               const float *__restrict__ w2,    const float *__restrict__ b2,
                               const float *__restrict__ ln3_g, const float *__restrict__ ln3_b,
                               const float *__restrict__ w3,    const float *__restrict__ b3) {
    int r = threadIdx.x;
    if (r >= 225) return;
    float in0 = (float)(r / 15 - 7), in1 = (float)(r % 15 - 7);
    float x[12], y[12];
#pragma unroll
    for (int j = 0; j < 12; j++) x[j] = in0 * w_proj[j] + in1 * w_proj[12 + j] + b_proj[j];
    ln_relu12(x, ln1_g, ln1_b);
#pragma unroll
    for (int j = 0; j < 12; j++) {
        float a = b1[j];
#pragma unroll
        for (int i = 0; i < 12; i++) a += x[i] * w1[i * 12 + j];
        y[j] = a;
    }
    ln_relu12(y, ln2_g, ln2_b);
#pragma unroll
    for (int j = 0; j < 12; j++) {
        float a = b2[j];
#pragma unroll
        for (int i = 0; i < 12; i++) a += y[i] * w2[i * 12 + j];
        x[j] = a;
    }
    ln_relu12(x, ln3_g, ln3_b);
#pragma unroll
    for (int h = 0; h < 6; h++) {
        float a = b3[h];
#pragma unroll
        for (int i = 0; i < 12; i++) a += x[i] * w3[i * 6 + h];
        g_rpb[h * 225 + r] = a;
    }
}

// CTA = (window, head); 128 threads / 4 warps; warp w owns S rows 16w..16w+15.
// Q/K/V in smem as fp16, 80-byte rows (40 halves = 20 u32) -> conflict-free ldmatrix.
__global__ __launch_bounds__(128, 4) void attn_kernel(const float *__restrict__ Q,
                                                      const float *__restrict__ K,
                                                      const float *__restrict__ V,
                                                      float *__restrict__ O) {
    __shared__ __align__(16) unsigned uQ[64 * 20];
    __shared__ __align__(16) unsigned uK[64 * 20];
    __shared__ __align__(16) unsigned uV[64 * 20];
    __shared__ float srpb[228];

    int head = blockIdx.x % 6, win = blockIdx.x / 6;
    int b = win >> 10, whb = (win >> 5) & 31, wwb = win & 31;
    int tid = threadIdx.x, lane = tid & 31, w = tid >> 5;

    for (int i = tid; i < 225; i += 128) srpb[i] = g_rpb[head * 225 + i];

    long base = ((long)b << 16) * 192 + head * 32;
    int r0 = whb << 3, c0 = wwb << 3;

    // ---- load fp32 -> fp16 smem (coalesced 128B segments per pixel row) ----
    int cpair = tid & 15;        // channel pair: ch = 2*cpair, 2*cpair+1
    int prow  = tid >> 4;        // 0..7
#pragma unroll
    for (int i = 0; i < 8; i++) {
        int p = prow + 8 * i;
        long g = base + (long)((r0 + (p >> 3)) * 256 + c0 + (p & 7)) * 192 + 2 * cpair;
        float2 fq = *reinterpret_cast<const float2 *>(Q + g);
        float2 fk = *reinterpret_cast<const float2 *>(K + g);
        float2 fv = *reinterpret_cast<const float2 *>(V + g);
        uQ[p * 20 + cpair] = pkh2(fq.x * QK_SCALE, fq.y * QK_SCALE);
        uK[p * 20 + cpair] = pkh2(fk.x, fk.y);
        uV[p * 20 + cpair] = pkh2(fv.x, fv.y);
    }
    __syncthreads();

    unsigned bQ = smem_u32(uQ), bK = smem_u32(uK), bV = smem_u32(uV);

    // ---- S = Q K^T (+rpb later): m16 x n64, k32 ----
    float c[8][4];
#pragma unroll
    for (int t = 0; t < 8; t++) { c[t][0] = 0.f; c[t][1] = 0.f; c[t][2] = 0.f; c[t][3] = 0.f; }
#pragma unroll
    for (int kk = 0; kk < 2; kk++) {
        uint4 a = ldm4(bQ + (16 * w + (lane & 15)) * 80 + kk * 32 + (lane >> 4) * 16);
#pragma unroll
        for (int nb = 0; nb < 4; nb++) {
            uint4 kf = ldm4(bK + (16 * nb + (lane & 15)) * 80 + kk * 32 + (lane >> 4) * 16);
            mmaf16(c[2 * nb],     a, kf.x, kf.z);
            mmaf16(c[2 * nb + 1], a, kf.y, kf.w);
        }
    }

    // ---- + rpb ----
    int j2 = (lane & 3) * 2, e = lane >> 2;
    int djA = e + 7 - j2;
#pragma unroll
    for (int t = 0; t < 8; t++) {
        int di0 = (2 * w + 7 - t) * 15;
        c[t][0] += srpb[di0 + djA];
        c[t][1] += srpb[di0 + djA - 1];
        c[t][2] += srpb[di0 + 15 + djA];
        c[t][3] += srpb[di0 + 15 + djA - 1];
    }

    // ---- softmax (rows e0 = 16w+e and e1 = e0+8), quad shfl reductions ----
    float mx0 = c[0][0], mx1 = c[0][2];
#pragma unroll
    for (int t = 0; t < 8; t++) {
        mx0 = fmaxf(mx0, fmaxf(c[t][0], c[t][1]));
        mx1 = fmaxf(mx1, fmaxf(c[t][2], c[t][3]));
    }
    mx0 = fmaxf(mx0, __shfl_xor_sync(0xffffffffu, mx0, 1));
    mx0 = fmaxf(mx0, __shfl_xor_sync(0xffffffffu, mx0, 2));
    mx1 = fmaxf(mx1, __shfl_xor_sync(0xffffffffu, mx1, 1));
    mx1 = fmaxf(mx1, __shfl_xor_sync(0xffffffffu, mx1, 2));
    float s0 = 0.f, s1 = 0.f;
#pragma unroll
    for (int t = 0; t < 8; t++) {
        c[t][0] = __expf(c[t][0] - mx0); s0 += c[t][0];
        c[t][1] = __expf(c[t][1] - mx0); s0 += c[t][1];
        c[t][2] = __expf(c[t][2] - mx1); s1 += c[t][2];
        c[t][3] = __expf(c[t][3] - mx1); s1 += c[t][3];
    }
    s0 += __shfl_xor_sync(0xffffffffu, s0, 1);
    s0 += __shfl_xor_sync(0xffffffffu, s0, 2);
    s1 += __shfl_xor_sync(0xffffffffu, s1, 1);
    s1 += __shfl_xor_sync(0xffffffffu, s1, 2);
    float inv0 = 1.0f / s0, inv1 = 1.0f / s1;

    // ---- O = P V : P stays in registers (C-frag == A-frag layout) ----
    float co[4][4];
#pragma unroll
    for (int t = 0; t < 4; t++) { co[t][0] = 0.f; co[t][1] = 0.f; co[t][2] = 0.f; co[t][3] = 0.f; }
#pragma unroll
    for (int K2 = 0; K2 < 4; K2++) {
        uint4 a;
        a.x = pkh2(c[2 * K2][0],     c[2 * K2][1]);
        a.y = pkh2(c[2 * K2][2],     c[2 * K2][3]);
        a.z = pkh2(c[2 * K2 + 1][0], c[2 * K2 + 1][1]);
        a.w = pkh2(c[2 * K2 + 1][2], c[2 * K2 + 1][3]);
#pragma unroll
        for (int nb2 = 0; nb2 < 2; nb2++) {
            uint4 vf = ldm4t(bV + (16 * K2 + (lane & 7) + ((lane >> 4) & 1) * 8) * 80 +
                             nb2 * 32 + ((lane >> 3) & 1) * 16);
            mmaf16(co[2 * nb2],     a, vf.x, vf.z);
            mmaf16(co[2 * nb2 + 1], a, vf.y, vf.w);
        }
    }

    // ---- epilogue: normalize + direct STG.64 (32B sectors) ----
    int n0 = 16 * w + e;             // row e0 ; e1 = n0 + 8
#pragma unroll
    for (int t = 0; t < 4; t++) {
        int ch = 8 * t + j2;
        long g0 = base + (long)((r0 + 2 * w) * 256 + c0 + e) * 192 + ch;
        long g1 = base + (long)((r0 + 2 * w + 1) * 256 + c0 + e) * 192 + ch;
        *reinterpret_cast<float2 *>(O + g0) = make_float2(co[t][0] * inv0, co[t][1] * inv0);
        *reinterpret_cast<float2 *>(O + g1) = make_float2(co[t][2] * inv1, co[t][3] * inv1);
    }
    (void)n0;
}

extern "C" void kernel_launch(void *const *d_in, const int *in_sizes, int n_in,
                              void *d_out, int out_size) {
    const float *q = (const float *)d_in[0];
    const float *k = (const float *)d_in[1];
    const float *v = (const float *)d_in[2];
    rpe_mlp_kernel<<<1, 256>>>((const float *)d_in[5], (const float *)d_in[6],
                               (const float *)d_in[7], (const float *)d_in[8],
                               (const float *)d_in[9], (const float *)d_in[10],
                               (const float *)d_in[11], (const float *)d_in[12],
                               (const float *)d_in[13], (const float *)d_in[14],
                               (const float *)d_in[15], (const float *)d_in[16],
                               (const float *)d_in[17], (const float *)d_in[18]);
    attn_kernel<<<24576, 128>>>(q, k, v, (float *)d_out);
}

// round 14
// speedup vs baseline: 3.9469x; 1.0415x over previous
#include <cuda_runtime.h>
#include <cuda_fp16.h>

__device__ float g_rpb[6 * 225];
#define QK_SCALE 0.17677669529663687f

static __device__ __forceinline__ unsigned smem_u32(const void *p) {
    unsigned a;
    asm("{ .reg .u64 t; cvta.to.shared.u64 t, %1; cvt.u32.u64 %0, t; }" : "=r"(a) : "l"(p));
    return a;
}
static __device__ __forceinline__ unsigned pkh2(float lo, float hi) {
    unsigned r;
    asm("cvt.rn.f16x2.f32 %0, %1, %2;" : "=r"(r) : "f"(hi), "f"(lo));
    return r;
}
static __device__ __forceinline__ uint4 ldm4(unsigned addr) {
    uint4 r;
    asm volatile("ldmatrix.sync.aligned.m8n8.x4.shared.b16 {%0,%1,%2,%3}, [%4];"
                 : "=r"(r.x), "=r"(r.y), "=r"(r.z), "=r"(r.w) : "r"(addr));
    return r;
}
static __device__ __forceinline__ uint4 ldm4t(unsigned addr) {
    uint4 r;
    asm volatile("ldmatrix.sync.aligned.m8n8.x4.trans.shared.b16 {%0,%1,%2,%3}, [%4];"
                 : "=r"(r.x), "=r"(r.y), "=r"(r.z), "=r"(r.w) : "r"(addr));
    return r;
}
static __device__ __forceinline__ void mmaf16(float *c, uint4 a, unsigned b0, unsigned b1) {
    asm volatile("mma.sync.aligned.m16n8k16.row.col.f32.f16.f16.f32 "
                 "{%0,%1,%2,%3}, {%4,%5,%6,%7}, {%8,%9}, {%0,%1,%2,%3};"
                 : "+f"(c[0]), "+f"(c[1]), "+f"(c[2]), "+f"(c[3])
                 : "r"(a.x), "r"(a.y), "r"(a.z), "r"(a.w), "r"(b0), "r"(b1));
}

static __device__ __forceinline__ void ln_relu12(float *x, const float *g, const float *b) {
    float m = 0.f;
#pragma unroll
    for (int j = 0; j < 12; j++) m += x[j];
    m *= (1.0f / 12.0f);
    float v = 0.f;
#pragma unroll
    for (int j = 0; j < 12; j++) { float d = x[j] - m; v += d * d; }
    v *= (1.0f / 12.0f);
    float inv = rsqrtf(v + 1e-5f);
#pragma unroll
    for (int j = 0; j < 12; j++) x[j] = fmaxf((x[j] - m) * inv * g[j] + b[j], 0.f);
}

__global__ void rpe_mlp_kernel(const float *__restrict__ w_proj, const float *__restrict__ b_proj,
                               const float *__restrict__ ln1_g, const float *__restrict__ ln1_b,
                               const float *__restrict__ w1,    const float *__restrict__ b1,
                               const float *__restrict__ ln2_g, const float *__restrict__ ln2_b,
                               const float *__restrict__ w2,    const float *__restrict__ b2,
                               const float *__restrict__ ln3_g, const float *__restrict__ ln3_b,
                               const float *__restrict__ w3,    const float *__restrict__ b3) {
    int r = threadIdx.x;
    if (r >= 225) return;
    float in0 = (float)(r / 15 - 7), in1 = (float)(r % 15 - 7);
    float x[12], y[12];
#pragma unroll
    for (int j = 0; j < 12; j++) x[j] = in0 * w_proj[j] + in1 * w_proj[12 + j] + b_proj[j];
    ln_relu12(x, ln1_g, ln1_b);
#pragma unroll
    for (int j = 0; j < 12; j++) {
        float a = b1[j];
#pragma unroll
        for (int i = 0; i < 12; i++) a += x[i] * w1[i * 12 + j];
        y[j] = a;
    }
    ln_relu12(y, ln2_g, ln2_b);
#pragma unroll
    for (int j = 0; j < 12; j++) {
        float a = b2[j];
#pragma unroll
        for (int i = 0; i < 12; i++) a += y[i] * w2[i * 12 + j];
        x[j] = a;
    }
    ln_relu12(x, ln3_g, ln3_b);
#pragma unroll
    for (int h = 0; h < 6; h++) {
        float a = b3[h];
#pragma unroll
        for (int i = 0; i < 12; i++) a += x[i] * w3[i * 6 + h];
        g_rpb[h * 225 + r] = a;
    }
}

// smem layout: fp16, 64 rows x 64B (16 u32), 16B unit u at phys (u ^ ((row>>1)&3)).
// -> ldmatrix 8-row phases hit (4*row + u^((row>>1)&3)) mod 8 = all-distinct slots: conflict-free.
static __device__ __forceinline__ unsigned swadr(unsigned base, int row, int u) {
    return base + row * 64 + ((u ^ ((row >> 1) & 3)) << 4);
}

// CTA = (window, head); 128 threads / 4 warps; warp w owns S rows 16w..16w+15.
__global__ __launch_bounds__(128, 6) void attn_kernel(const float *__restrict__ Q,
                                                      const float *__restrict__ K,
                                                      const float *__restrict__ V,
                                                      float *__restrict__ O) {
    __shared__ __align__(16) unsigned uQ[64 * 16];
    __shared__ __align__(16) unsigned uK[64 * 16];
    __shared__ __align__(16) unsigned uV[64 * 16];
    __shared__ float srpb[228];

    int head = blockIdx.x % 6, win = blockIdx.x / 6;
    int b = win >> 10, whb = (win >> 5) & 31, wwb = win & 31;
    int tid = threadIdx.x, lane = tid & 31, w = tid >> 5;

    for (int i = tid; i < 225; i += 128) srpb[i] = g_rpb[head * 225 + i];

    int base = b * (65536 * 192) + head * 32;     // 32-bit offsets (max < 2^26 floats)
    int r0 = whb << 3, c0 = wwb << 3;

    // ---- load f32->f16 smem: LDG.128, STS.64 into swizzled layout ----
    int cq = lane & 7;       // 16B chunk (4 channels)
    int psub = lane >> 3;    // pixel-within-group
#pragma unroll
    for (int i = 0; i < 4; i++) {
        int p = 16 * w + 4 * i + psub;
        int g = base + ((r0 + (p >> 3)) * 256 + c0 + (p & 7)) * 192 + cq * 4;
        float4 fq = *reinterpret_cast<const float4 *>(Q + g);
        float4 fk = *reinterpret_cast<const float4 *>(K + g);
        float4 fv = *reinterpret_cast<const float4 *>(V + g);
        int off = p * 16 + (((cq >> 1) ^ ((p >> 1) & 3)) << 2) + (cq & 1) * 2;
        *reinterpret_cast<uint2 *>(uQ + off) =
            make_uint2(pkh2(fq.x * QK_SCALE, fq.y * QK_SCALE), pkh2(fq.z * QK_SCALE, fq.w * QK_SCALE));
        *reinterpret_cast<uint2 *>(uK + off) = make_uint2(pkh2(fk.x, fk.y), pkh2(fk.z, fk.w));
        *reinterpret_cast<uint2 *>(uV + off) = make_uint2(pkh2(fv.x, fv.y), pkh2(fv.z, fv.w));
    }
    __syncthreads();

    unsigned bQ = smem_u32(uQ), bK = smem_u32(uK), bV = smem_u32(uV);

    // ---- S = Q K^T : m16 x n64, k32 ----
    float c[8][4];
#pragma unroll
    for (int t = 0; t < 8; t++) { c[t][0] = 0.f; c[t][1] = 0.f; c[t][2] = 0.f; c[t][3] = 0.f; }
#pragma unroll
    for (int kk = 0; kk < 2; kk++) {
        int uu = kk * 2 + (lane >> 4);
        uint4 a = ldm4(swadr(bQ, 16 * w + (lane & 15), uu));
#pragma unroll
        for (int nb = 0; nb < 4; nb++) {
            uint4 kf = ldm4(swadr(bK, 16 * nb + (lane & 15), uu));
            mmaf16(c[2 * nb],     a, kf.x, kf.z);
            mmaf16(c[2 * nb + 1], a, kf.y, kf.w);
        }
    }

    // ---- + rpb ----
    int j2 = (lane & 3) * 2, e = lane >> 2;
    int djA = e + 7 - j2;
#pragma unroll
    for (int t = 0; t < 8; t++) {
        int di0 = (2 * w + 7 - t) * 15;
        c[t][0] += srpb[di0 + djA];
        c[t][1] += srpb[di0 + djA - 1];
        c[t][2] += srpb[di0 + 15 + djA];
        c[t][3] += srpb[di0 + 15 + djA - 1];
    }

    // ---- softmax (rows e0 = 16w+e and e1 = e0+8), quad shfl reductions ----
    float mx0 = c[0][0], mx1 = c[0][2];
#pragma unroll
    for (int t = 0; t < 8; t++) {
        mx0 = fmaxf(mx0, fmaxf(c[t][0], c[t][1]));
        mx1 = fmaxf(mx1, fmaxf(c[t][2], c[t][3]));
    }
    mx0 = fmaxf(mx0, __shfl_xor_sync(0xffffffffu, mx0, 1));
    mx0 = fmaxf(mx0, __shfl_xor_sync(0xffffffffu, mx0, 2));
    mx1 = fmaxf(mx1, __shfl_xor_sync(0xffffffffu, mx1, 1));
    mx1 = fmaxf(mx1, __shfl_xor_sync(0xffffffffu, mx1, 2));
    float s0 = 0.f, s1 = 0.f;
#pragma unroll
    for (int t = 0; t < 8; t++) {
        c[t][0] = __expf(c[t][0] - mx0); s0 += c[t][0];
        c[t][1] = __expf(c[t][1] - mx0); s0 += c[t][1];
        c[t][2] = __expf(c[t][2] - mx1); s1 += c[t][2];
        c[t][3] = __expf(c[t][3] - mx1); s1 += c[t][3];
    }
    s0 += __shfl_xor_sync(0xffffffffu, s0, 1);
    s0 += __shfl_xor_sync(0xffffffffu, s0, 2);
    s1 += __shfl_xor_sync(0xffffffffu, s1, 1);
    s1 += __shfl_xor_sync(0xffffffffu, s1, 2);
    float inv0 = 1.0f / s0, inv1 = 1.0f / s1;

    // ---- O = P V : P stays in registers (C-frag == A-frag layout) ----
    float co[4][4];
#pragma unroll
    for (int t = 0; t < 4; t++) { co[t][0] = 0.f; co[t][1] = 0.f; co[t][2] = 0.f; co[t][3] = 0.f; }
#pragma unroll
    for (int K2 = 0; K2 < 4; K2++) {
        uint4 a;
        a.x = pkh2(c[2 * K2][0],     c[2 * K2][1]);
        a.y = pkh2(c[2 * K2][2],     c[2 * K2][3]);
        a.z = pkh2(c[2 * K2 + 1][0], c[2 * K2 + 1][1]);
        a.w = pkh2(c[2 * K2 + 1][2], c[2 * K2 + 1][3]);
        int rowv = 16 * K2 + (lane & 7) + ((lane >> 4) & 1) * 8;
#pragma unroll
        for (int nb2 = 0; nb2 < 2; nb2++) {
            uint4 vf = ldm4t(swadr(bV, rowv, nb2 * 2 + ((lane >> 3) & 1)));
            mmaf16(co[2 * nb2],     a, vf.x, vf.z);
            mmaf16(co[2 * nb2 + 1], a, vf.y, vf.w);
        }
    }

    // ---- epilogue: normalize + direct STG.64 (full 32B sectors per quad) ----
#pragma unroll
    for (int t = 0; t < 4; t++) {
        int ch = 8 * t + j2;
        int g0 = base + ((r0 + 2 * w) * 256 + c0 + e) * 192 + ch;
        int g1 = base + ((r0 + 2 * w + 1) * 256 + c0 + e) * 192 + ch;
        *reinterpret_cast<float2 *>(O + g0) = make_float2(co[t][0] * inv0, co[t][1] * inv0);
        *reinterpret_cast<float2 *>(O + g1) = make_float2(co[t][2] * inv1, co[t][3] * inv1);
    }
}

extern "C" void kernel_launch(void *const *d_in, const int *in_sizes, int n_in,
                              void *d_out, int out_size) {
    const float *q = (const float *)d_in[0];
    const float *k = (const float *)d_in[1];
    const float *v = (const float *)d_in[2];
    rpe_mlp_kernel<<<1, 256>>>((const float *)d_in[5], (const float *)d_in[6],
                               (const float *)d_in[7], (const float *)d_in[8],
                               (const float *)d_in[9], (const float *)d_in[10],
                               (const float *)d_in[11], (const float *)d_in[12],
                               (const float *)d_in[13], (const float *)d_in[14],
                               (const float *)d_in[15], (const float *)d_in[16],
                               (const float *)d_in[17], (const float *)d_in[18]);
    attn_kernel<<<24576, 128>>>(q, k, v, (float *)d_out);
}